// round 1
// baseline (speedup 1.0000x reference)
#include <cuda_runtime.h>
#include <math.h>

// ---------------------------------------------------------------------------
// Problem shapes (fixed):
//   x:       (16, 64, 224, 224) fp32
//   spec:    (64, 64, 3, 3)     fp32
//   alpha:   scalar fp32
//   polar_w: (2,) fp32
//   out:     (16, 64, 224, 224) fp32  -- 3x3 conv, pad 1, weights from FrFT
// ---------------------------------------------------------------------------

#define NB    16
#define C     64
#define HW    224

__device__ float g_w[C * C * 9];   // generated conv weights [co][ci][tap]

// ---------------------------------------------------------------------------
// Weight generation: K = pw0*|F S F^T| + pw1*angle(F S F^T)/pi
// F is the 3x3 complex FrFT matrix (chirp-z shear form, N=3, n=[-2,-1,0]).
// 16 blocks x 256 threads: thread 0 of each block builds F (in double),
// then each thread handles one (co,ci) pair.
// ---------------------------------------------------------------------------
__global__ void gen_weights_kernel(const float* __restrict__ spec,
                                   const float* __restrict__ alpha_p,
                                   const float* __restrict__ polar_w)
{
    __shared__ float Fr[3][3], Fi[3][3];

    if (threadIdx.x == 0) {
        const double PI = 3.14159265358979323846;
        double a = (double)alpha_p[0];
        const double EPS = 1e-4;
        if (a < EPS)        a = EPS;
        if (a > 2.0 - EPS)  a = 2.0 - EPS;

        double tan_a2 = tan(a * PI / 4.0);
        double sin_a  = sin(a * PI / 2.0);
        // n = arange((-3)//2, 3//2) = [-2,-1,0];  n^2:
        const double n2[3] = {4.0, 1.0, 0.0};
        double c1r[3], c1i[3], c2r[3], c2i[3];
        for (int j = 0; j < 3; j++) {
            double t1 = -PI * n2[j] * tan_a2 / 3.0;
            c1r[j] = cos(t1); c1i[j] = sin(t1);
            double t2 = -PI * n2[j] / (3.0 * sin_a);
            c2r[j] = cos(t2); c2i[j] = sin(t2);
        }
        double scale = 1.0 / sqrt(fabs(sin_a) + 1e-12);

        // Apply transform to basis vectors e_k to get columns of F.
        for (int k = 0; k < 3; k++) {
            // ifftshift(e_k): delta lands at p = (k+2)%3
            int p = (k + 2) % 3;
            double xr = c1r[p], xi = c1i[p];
            double Xr[3], Xi[3];
            for (int m = 0; m < 3; m++) {
                double ang = -2.0 * PI * (double)(m * p) / 3.0;
                double er = cos(ang), ei = sin(ang);
                double tr = er * xr - ei * xi;
                double ti = er * xi + ei * xr;
                Xr[m] = tr * c2r[m] - ti * c2i[m];   // multiply by c2
                Xi[m] = tr * c2i[m] + ti * c2r[m];
            }
            for (int j = 0; j < 3; j++) {
                double yr = 0.0, yi = 0.0;
                for (int m = 0; m < 3; m++) {
                    double ang = 2.0 * PI * (double)(j * m) / 3.0;
                    double er = cos(ang), ei = sin(ang);
                    yr += er * Xr[m] - ei * Xi[m];
                    yi += er * Xi[m] + ei * Xr[m];
                }
                yr /= 3.0; yi /= 3.0;                 // ifft 1/N
                double fr = yr * c1r[j] - yi * c1i[j];
                double fi = yr * c1i[j] + yi * c1r[j];
                fr *= scale; fi *= scale;
                int io = (j + 1) % 3;                 // fftshift: y[j] -> index (j+1)%3
                Fr[io][k] = (float)fr;
                Fi[io][k] = (float)fi;
            }
        }
    }
    __syncthreads();

    int pidx = blockIdx.x * blockDim.x + threadIdx.x;   // (co*64 + ci)
    if (pidx >= C * C) return;

    float s[3][3];
#pragma unroll
    for (int r = 0; r < 3; r++)
#pragma unroll
        for (int k = 0; k < 3; k++)
            s[r][k] = spec[pidx * 9 + r * 3 + k];

    // T = S * F^T   (S real):  T[r][j] = sum_k s[r][k] * F[j][k]
    float Tr[3][3], Ti[3][3];
#pragma unroll
    for (int r = 0; r < 3; r++)
#pragma unroll
        for (int j = 0; j < 3; j++) {
            float tr = 0.f, ti = 0.f;
#pragma unroll
            for (int k = 0; k < 3; k++) {
                tr += s[r][k] * Fr[j][k];
                ti += s[r][k] * Fi[j][k];
            }
            Tr[r][j] = tr; Ti[r][j] = ti;
        }

    const float pw0 = polar_w[0];
    const float pw1 = polar_w[1];
    const float INV_PI = 0.318309886183790672f;

    // Y = F * T
#pragma unroll
    for (int i = 0; i < 3; i++)
#pragma unroll
        for (int j = 0; j < 3; j++) {
            float yr = 0.f, yi = 0.f;
#pragma unroll
            for (int r = 0; r < 3; r++) {
                yr += Fr[i][r] * Tr[r][j] - Fi[i][r] * Ti[r][j];
                yi += Fr[i][r] * Ti[r][j] + Fi[i][r] * Tr[r][j];
            }
            float mag = sqrtf(yr * yr + yi * yi);
            float ang = atan2f(yi, yr) * INV_PI;
            g_w[pidx * 9 + i * 3 + j] = pw0 * mag + pw1 * ang;
        }
}

// ---------------------------------------------------------------------------
// Direct 3x3 conv, fp32, register-tiled.
//   Block: 256 threads, output tile = 32 co x 16 h x 32 w.
//   Thread: 8 co x 2 h x 4 w outputs (h/w strided by 8 for bank friendliness).
//   ci processed in chunks of 8 through shared memory.
// ---------------------------------------------------------------------------
#define TH       16
#define TW       32
#define CO_BLK   32
#define CI_CHK   8
#define ROWS     18          // TH + 2 halo
#define COLSLD   34          // TW + 2 halo (loaded)
#define RSTRIDE  40          // padded row stride (8 mod 32 -> conflict-free)

__global__ __launch_bounds__(256, 2)
void conv3x3_kernel(const float* __restrict__ x, float* __restrict__ out)
{
    __shared__ float stile[CI_CHK][ROWS][RSTRIDE];
    __shared__ float swt[CO_BLK][CI_CHK][9];

    const int t   = threadIdx.x;
    const int w0  = blockIdx.x * TW;
    const int h0  = blockIdx.y * TH;
    const int n   = blockIdx.z >> 1;
    const int co0 = (blockIdx.z & 1) * CO_BLK;

    const int cog = t >> 6;        // 0..3  -> co group of 8
    const int pos = t & 63;
    const int py  = pos >> 3;      // 0..7
    const int px  = pos & 7;       // 0..7

    float acc[8][2][4];
#pragma unroll
    for (int o = 0; o < 8; o++)
#pragma unroll
        for (int iy = 0; iy < 2; iy++)
#pragma unroll
            for (int ix = 0; ix < 4; ix++)
                acc[o][iy][ix] = 0.f;

    const float* xn = x + (size_t)n * C * HW * HW;

    for (int ci0 = 0; ci0 < C; ci0 += CI_CHK) {
        __syncthreads();
        // Load input tile (with halo, zero-padded at image borders)
        for (int idx = t; idx < CI_CHK * ROWS * COLSLD; idx += 256) {
            int ci  = idx / (ROWS * COLSLD);
            int rem = idx - ci * (ROWS * COLSLD);
            int r   = rem / COLSLD;
            int c   = rem - r * COLSLD;
            int gh  = h0 - 1 + r;
            int gw  = w0 - 1 + c;
            float v = 0.f;
            if (gh >= 0 && gh < HW && gw >= 0 && gw < HW)
                v = xn[((size_t)(ci0 + ci) * HW + gh) * HW + gw];
            stile[ci][r][c] = v;
        }
        // Load weight chunk
        for (int idx = t; idx < CO_BLK * CI_CHK * 9; idx += 256) {
            int co  = idx / (CI_CHK * 9);
            int rem = idx - co * (CI_CHK * 9);
            int ci  = rem / 9;
            int tap = rem - ci * 9;
            swt[co][ci][tap] = g_w[((co0 + co) * C + ci0 + ci) * 9 + tap];
        }
        __syncthreads();

        for (int cc = 0; cc < CI_CHK; cc++) {
#pragma unroll
            for (int ky = 0; ky < 3; ky++) {
#pragma unroll
                for (int kx = 0; kx < 3; kx++) {
                    float wv[8];
#pragma unroll
                    for (int o = 0; o < 8; o++)
                        wv[o] = swt[cog * 8 + o][cc][ky * 3 + kx];
                    float xv[2][4];
#pragma unroll
                    for (int iy = 0; iy < 2; iy++)
#pragma unroll
                        for (int ix = 0; ix < 4; ix++)
                            xv[iy][ix] = stile[cc][py + iy * 8 + ky][px + ix * 8 + kx];
#pragma unroll
                    for (int o = 0; o < 8; o++)
#pragma unroll
                        for (int iy = 0; iy < 2; iy++)
#pragma unroll
                            for (int ix = 0; ix < 4; ix++)
                                acc[o][iy][ix] = fmaf(wv[o], xv[iy][ix], acc[o][iy][ix]);
                }
            }
        }
    }

    float* outn = out + (size_t)n * C * HW * HW;
#pragma unroll
    for (int o = 0; o < 8; o++) {
        const int co = co0 + cog * 8 + o;
#pragma unroll
        for (int iy = 0; iy < 2; iy++) {
            const int h = h0 + py + iy * 8;
#pragma unroll
            for (int ix = 0; ix < 4; ix++) {
                const int w = w0 + px + ix * 8;
                outn[((size_t)co * HW + h) * HW + w] = acc[o][iy][ix];
            }
        }
    }
}

// ---------------------------------------------------------------------------
// Inputs (metadata order): x, spec, alpha, polar_w
// ---------------------------------------------------------------------------
extern "C" void kernel_launch(void* const* d_in, const int* in_sizes, int n_in,
                              void* d_out, int out_size)
{
    const float* x       = (const float*)d_in[0];
    const float* spec    = (const float*)d_in[1];
    const float* alpha   = (const float*)d_in[2];
    const float* polar_w = (const float*)d_in[3];
    float* out = (float*)d_out;

    gen_weights_kernel<<<16, 256>>>(spec, alpha, polar_w);

    dim3 grid(HW / TW, HW / TH, NB * 2);
    conv3x3_kernel<<<grid, 256>>>(x, out);
}

// round 4
// speedup vs baseline: 2.5925x; 2.5925x over previous
#include <cuda_runtime.h>
#include <cuda_fp16.h>
#include <math.h>
#include <stdint.h>

// ---------------------------------------------------------------------------
// Shapes: x (16,64,224,224) f32, spec (64,64,3,3) f32, alpha f32, polar_w (2)
// out (16,64,224,224) f32 = conv3x3(x, FrFT-kernel(spec)), pad 1
// ---------------------------------------------------------------------------
#define NBATCH 16
#define C      64
#define HW     224
#define HW2    (HW*HW)

#define HTILE  4            // output rows per CTA
#define MROWS  6            // staged rows = HTILE + 2
#define MTILE  128          // output pixels (M) per row-tile
#define SLOTS  130          // staged pixels per row
#define XSTR   70           // ci stride in halfs (padded from 64)
#define KCHUNKS 36          // K = 9 taps * 64 ci = 576 -> 36 chunks of 16

#define B_BYTES  (64*576*2)                 // 73728: fp16 weights, fragment layout
#define XS_BYTES (MROWS*SLOTS*XSTR*2)       // 109200
#define SMEM_DYN (B_BYTES + XS_BYTES)       // 182928

// fp16 weights in mma-fragment layout: [ntile(8)][kc(36)][lane(32)][j(2)][c(2)] u16
__device__ unsigned short gBf[64 * 576];

// ---------------------------------------------------------------------------
// Weight gen: w[co][ci][ky][kx] = pw0*|F S F^T| + pw1*angle(F S F^T)/pi
// F = 3x3 complex FrFT matrix (chirp-z shear, N=3), built in double.
// Scatter each value into gBf at its mma fragment slot.
//   k = tap*64 + ci, tap = kx*3 + ky
// ---------------------------------------------------------------------------
__global__ void gen_weights_kernel(const float* __restrict__ spec,
                                   const float* __restrict__ alpha_p,
                                   const float* __restrict__ polar_w)
{
    __shared__ float Fr[3][3], Fi[3][3];

    if (threadIdx.x == 0) {
        const double PI = 3.14159265358979323846;
        double a = (double)alpha_p[0];
        const double EPS = 1e-4;
        if (a < EPS)       a = EPS;
        if (a > 2.0 - EPS) a = 2.0 - EPS;
        double tan_a2 = tan(a * PI / 4.0);
        double sin_a  = sin(a * PI / 2.0);
        const double n2[3] = {4.0, 1.0, 0.0};
        double c1r[3], c1i[3], c2r[3], c2i[3];
        for (int j = 0; j < 3; j++) {
            double t1 = -PI * n2[j] * tan_a2 / 3.0;
            c1r[j] = cos(t1); c1i[j] = sin(t1);
            double t2 = -PI * n2[j] / (3.0 * sin_a);
            c2r[j] = cos(t2); c2i[j] = sin(t2);
        }
        double scale = 1.0 / sqrt(fabs(sin_a) + 1e-12);
        for (int k = 0; k < 3; k++) {
            int p = (k + 2) % 3;                      // ifftshift of basis e_k
            double xr = c1r[p], xi = c1i[p];
            double Xr[3], Xi[3];
            for (int m = 0; m < 3; m++) {
                double ang = -2.0 * PI * (double)(m * p) / 3.0;
                double er = cos(ang), ei = sin(ang);
                double tr = er * xr - ei * xi;
                double ti = er * xi + ei * xr;
                Xr[m] = tr * c2r[m] - ti * c2i[m];
                Xi[m] = tr * c2i[m] + ti * c2r[m];
            }
            for (int j = 0; j < 3; j++) {
                double yr = 0.0, yi = 0.0;
                for (int m = 0; m < 3; m++) {
                    double ang = 2.0 * PI * (double)(j * m) / 3.0;
                    double er = cos(ang), ei = sin(ang);
                    yr += er * Xr[m] - ei * Xi[m];
                    yi += er * Xi[m] + ei * Xr[m];
                }
                yr /= 3.0; yi /= 3.0;                 // ifft 1/N
                double fr = yr * c1r[j] - yi * c1i[j];
                double fi = yr * c1i[j] + yi * c1r[j];
                fr *= scale; fi *= scale;
                int io = (j + 1) % 3;                 // fftshift
                Fr[io][k] = (float)fr;
                Fi[io][k] = (float)fi;
            }
        }
    }
    __syncthreads();

    int pidx = blockIdx.x * blockDim.x + threadIdx.x;   // co*64 + ci
    if (pidx >= C * C) return;
    int co = pidx >> 6, ci = pidx & 63;

    float s[3][3];
#pragma unroll
    for (int r = 0; r < 3; r++)
#pragma unroll
        for (int k = 0; k < 3; k++)
            s[r][k] = spec[pidx * 9 + r * 3 + k];

    // T = S * F^T
    float Tr[3][3], Ti[3][3];
#pragma unroll
    for (int r = 0; r < 3; r++)
#pragma unroll
        for (int j = 0; j < 3; j++) {
            float tr = 0.f, ti = 0.f;
#pragma unroll
            for (int k = 0; k < 3; k++) {
                tr += s[r][k] * Fr[j][k];
                ti += s[r][k] * Fi[j][k];
            }
            Tr[r][j] = tr; Ti[r][j] = ti;
        }

    const float pw0 = polar_w[0];
    const float pw1 = polar_w[1];
    const float INV_PI = 0.318309886183790672f;

#pragma unroll
    for (int i = 0; i < 3; i++)        // i = ky
#pragma unroll
        for (int j = 0; j < 3; j++) {  // j = kx
            float yr = 0.f, yi = 0.f;
#pragma unroll
            for (int r = 0; r < 3; r++) {
                yr += Fr[i][r] * Tr[r][j] - Fi[i][r] * Ti[r][j];
                yi += Fr[i][r] * Ti[r][j] + Fi[i][r] * Tr[r][j];
            }
            float mag = sqrtf(yr * yr + yi * yi);
            float ang = atan2f(yi, yr) * INV_PI;
            float w   = pw0 * mag + pw1 * ang;

            // scatter into fragment layout
            int tap  = j * 3 + i;                 // kx*3 + ky
            int kc   = tap * 4 + (ci >> 4);       // k-chunk
            int cil  = ci & 15;                   // k within chunk
            int lane = ((co & 7) << 2) | ((cil & 7) >> 1);
            int jj   = cil >> 3;
            int cpos = ci & 1;
            int idx  = ((((co >> 3) * KCHUNKS + kc) * 32 + lane) * 2 + jj) * 2 + cpos;
            gBf[idx] = __half_as_ushort(__float2half_rn(w));
        }
}

// ---------------------------------------------------------------------------
// HMMA conv kernel. 256 threads, grid (2 wtiles, 56 hblocks, 16 batch).
// Warp grid 4(M) x 2(N): warp tile = 32 px x 32 co.
// ---------------------------------------------------------------------------
#define MMA16816(d, a, bx, by)                                               \
    asm volatile("mma.sync.aligned.m16n8k16.row.col.f32.f16.f16.f32 "        \
        "{%0,%1,%2,%3}, {%4,%5,%6,%7}, {%8,%9}, {%0,%1,%2,%3};"              \
        : "+f"((d)[0]), "+f"((d)[1]), "+f"((d)[2]), "+f"((d)[3])             \
        : "r"((a)[0]), "r"((a)[1]), "r"((a)[2]), "r"((a)[3]),                \
          "r"(bx), "r"(by))

__global__ __launch_bounds__(256, 1)
void conv_hmma_kernel(const float* __restrict__ x, float* __restrict__ out)
{
    extern __shared__ char smem[];
    unsigned short* Bs = (unsigned short*)smem;            // fragment-layout weights
    __half* xs = (__half*)(smem + B_BYTES);                // [row][slot][ci] (XSTR)

    const int tid    = threadIdx.x;
    const int lane   = tid & 31;
    const int warp   = tid >> 5;
    const int warp_m = warp & 3;
    const int warp_n = warp >> 2;

    const int w0 = blockIdx.x * 96;            // 0 or 96
    const int h0 = blockIdx.y * HTILE;
    const int nb = blockIdx.z;
    const float* xn = x + (size_t)nb * C * HW2;

    // ---- stage weights ----
    {
        const uint4* src = (const uint4*)gBf;
        uint4* dst = (uint4*)Bs;
        for (int i = tid; i < B_BYTES / 16; i += 256) dst[i] = src[i];
    }

    // ---- stage input tile: rows h0-1 .. h0+4, slots = w0-1 .. w0+128, ci-fast ----
    for (int task = warp; task < MROWS * C; task += 8) {
        int row = task >> 6;
        int ci  = task & 63;
        int hh  = h0 - 1 + row;
        bool okh = ((unsigned)hh < (unsigned)HW);
        const float* p = xn + (size_t)ci * HW2 + (size_t)hh * HW;
#pragma unroll
        for (int it = 0; it < 5; it++) {
            int px = it * 32 + lane;
            if (px < SLOTS) {
                int gw = w0 - 1 + px;
                float v = 0.f;
                if (okh && (unsigned)gw < (unsigned)HW) v = p[gw];
                xs[(row * SLOTS + px) * XSTR + ci] = __float2half_rn(v);
            }
        }
    }
    __syncthreads();

    const int m_base = warp_m * 32;
    const int lane_m = lane >> 2;
    const int lane_k = (lane & 3) << 1;

    for (int r = 0; r < HTILE; r++) {
        float acc[2][4][4];
#pragma unroll
        for (int mt = 0; mt < 2; mt++)
#pragma unroll
            for (int nt = 0; nt < 4; nt++)
#pragma unroll
                for (int q = 0; q < 4; q++)
                    acc[mt][nt][q] = 0.f;

        const __half* rb[3];
#pragma unroll
        for (int ky = 0; ky < 3; ky++)
            rb[ky] = &xs[((r + ky) * SLOTS + m_base + lane_m) * XSTR + lane_k];

#pragma unroll
        for (int tap = 0; tap < 9; tap++) {
            const int kx = tap / 3, ky = tap % 3;   // tap = kx*3 + ky
            const __half* abase = rb[ky] + kx * XSTR;
#pragma unroll
            for (int cib = 0; cib < 4; cib++) {
                const int kc = tap * 4 + cib;
                uint32_t a[2][4];
#pragma unroll
                for (int mt = 0; mt < 2; mt++) {
                    const __half* ap = abase + mt * 16 * XSTR + cib * 16;
                    a[mt][0] = *(const uint32_t*)(ap);
                    a[mt][1] = *(const uint32_t*)(ap + 8 * XSTR);
                    a[mt][2] = *(const uint32_t*)(ap + 8);
                    a[mt][3] = *(const uint32_t*)(ap + 8 * XSTR + 8);
                }
#pragma unroll
                for (int nt = 0; nt < 4; nt++) {
                    const int ntile = warp_n * 4 + nt;
                    const uint2 b = *(const uint2*)
                        &Bs[(((ntile * KCHUNKS) + kc) * 32 + lane) * 4];
#pragma unroll
                    for (int mt = 0; mt < 2; mt++)
                        MMA16816(acc[mt][nt], a[mt], b.x, b.y);
                }
            }
        }

        // ---- store row r ----
        const int h = h0 + r;
#pragma unroll
        for (int mt = 0; mt < 2; mt++) {
            const int gw1 = w0 + m_base + mt * 16 + lane_m;   // d0/d1 pixel
            const int gw2 = gw1 + 8;                          // d2/d3 pixel
            const bool p1 = (w0 == 0) || (gw1 >= 128);
            const bool p2 = (w0 == 0) || (gw2 >= 128);
#pragma unroll
            for (int nt = 0; nt < 4; nt++) {
                const int co = warp_n * 32 + nt * 8 + lane_k;
                float* op = out + (((size_t)nb * C + co) * HW + h) * HW;
                if (p1) {
                    op[gw1]        = acc[mt][nt][0];
                    (op + HW2)[gw1] = acc[mt][nt][1];
                }
                if (p2) {
                    op[gw2]        = acc[mt][nt][2];
                    (op + HW2)[gw2] = acc[mt][nt][3];
                }
            }
        }
    }
}

// ---------------------------------------------------------------------------
// Inputs (metadata order): x, spec, alpha, polar_w
// ---------------------------------------------------------------------------
extern "C" void kernel_launch(void* const* d_in, const int* in_sizes, int n_in,
                              void* d_out, int out_size)
{
    const float* x       = (const float*)d_in[0];
    const float* spec    = (const float*)d_in[1];
    const float* alpha   = (const float*)d_in[2];
    const float* polar_w = (const float*)d_in[3];
    float* out = (float*)d_out;

    cudaFuncSetAttribute(conv_hmma_kernel,
                         cudaFuncAttributeMaxDynamicSharedMemorySize, SMEM_DYN);

    gen_weights_kernel<<<16, 256>>>(spec, alpha, polar_w);

    dim3 grid(2, HW / HTILE, NBATCH);
    conv_hmma_kernel<<<grid, 256, SMEM_DYN>>>(x, out);
}